// round 1
// baseline (speedup 1.0000x reference)
#include <cuda_runtime.h>

#define BB   32
#define D3D  256
#define D2D  768
#define DT   3072
#define PP   3072
#define SS   256
#define TT   512
#define SEQ  256
#define XK   (PP*3)     // 9216

#define KS2  48         // k-split for u (p-chunks of 64)
#define TS   8          // text splits per batch
#define KS7  24         // k-split for fused GEMM (k-chunk 384)

// ---- scratch (static device memory; no allocation) ----
__device__ float g_f3p[BB*PP];              // [32,3072]
__device__ float g_upart[KS2*BB*D2D];       // partial u
__device__ float g_g[BB*D2D];               // weighted feat_2d sum
__device__ float g_p2d[BB*PP];              // pooled_2d
__device__ float g_mpart[BB*TS];
__device__ float g_zpart[BB*TS];
__device__ float g_vpart[BB*TS*PP];         // unnormalized pooled partials
__device__ float g_ptext[BB*PP];            // pooled_text
__device__ float g_x[BB*XK];                // concat input to fused GEMM
__device__ float g_fpart[KS7*BB*PP];        // fused GEMM partials

__device__ __forceinline__ float warp_sum(float v){
    #pragma unroll
    for (int o = 16; o; o >>= 1) v += __shfl_xor_sync(0xffffffffu, v, o);
    return v;
}

// ---------------- K1: f3p = feat_3d @ W3d^T + b3d  [32,3072] ----------------
__global__ void k1_f3p(const float* __restrict__ f3, const float* __restrict__ W3,
                       const float* __restrict__ b3){
    int b = blockIdx.x / 12, pt = blockIdx.x % 12;
    int p0 = pt * 256;
    __shared__ float fs[D3D];
    int tid = threadIdx.x, w = tid >> 5, lane = tid & 31;
    fs[tid] = f3[b*D3D + tid];
    __syncthreads();
    const float4* fs4 = (const float4*)fs;
    for (int i = 0; i < 32; i++){
        int p = p0 + w*32 + i;
        const float4* row = (const float4*)(W3 + p*D3D);
        float s = 0.f;
        #pragma unroll
        for (int j = 0; j < 2; j++){
            float4 a = row[lane + 32*j], c = fs4[lane + 32*j];
            s += a.x*c.x + a.y*c.y + a.z*c.z + a.w*c.w;
        }
        s = warp_sum(s);
        if (!lane) g_f3p[b*PP + p] = s + b3[p];
    }
}

// ---------------- K2: u[b,d] = sum_p f3p[b,p]*W2d[p,d] (partials) ----------------
__global__ void k2_u(const float* __restrict__ W2){
    int dt = blockIdx.x % 3, ks = blockIdx.x / 3;
    int tid = threadIdx.x;
    int d = dt*256 + tid;
    int pbase = ks * 64;
    __shared__ float fs[BB*64];   // [b][pp]
    for (int e = tid; e < BB*64; e += 256){
        int bb = e >> 6, pp = e & 63;
        fs[e] = g_f3p[bb*PP + pbase + pp];
    }
    __syncthreads();
    float acc[BB];
    #pragma unroll
    for (int bb = 0; bb < BB; bb++) acc[bb] = 0.f;
    const float4* fs4 = (const float4*)fs;
    for (int pp = 0; pp < 64; pp += 4){
        float w0 = W2[(pbase+pp+0)*D2D + d];
        float w1 = W2[(pbase+pp+1)*D2D + d];
        float w2 = W2[(pbase+pp+2)*D2D + d];
        float w3 = W2[(pbase+pp+3)*D2D + d];
        #pragma unroll
        for (int bb = 0; bb < BB; bb++){
            float4 f = fs4[bb*16 + (pp >> 2)];
            acc[bb] += f.x*w0 + f.y*w1 + f.z*w2 + f.w*w3;
        }
    }
    #pragma unroll
    for (int bb = 0; bb < BB; bb++)
        g_upart[(ks*BB + bb)*D2D + d] = acc[bb];
}

// ---- K3: scores_s = feat_2d . u, softmax, g = sum_s w_s feat_2d  (one block / b) ----
__global__ void k3_s2d(const float* __restrict__ f2d){
    int b = blockIdx.x;
    __shared__ float us[D2D];
    __shared__ float sc[SS];
    __shared__ float red[9];
    int tid = threadIdx.x, w = tid >> 5, lane = tid & 31;
    for (int d = tid; d < D2D; d += 256){
        float s = 0.f;
        for (int ks = 0; ks < KS2; ks++) s += g_upart[(ks*BB + b)*D2D + d];
        us[d] = s;
    }
    __syncthreads();
    const float4* us4 = (const float4*)us;
    for (int i = 0; i < 32; i++){
        int si = w*32 + i;
        const float4* row = (const float4*)(f2d + (b*SS + si)*D2D);
        float s = 0.f;
        #pragma unroll
        for (int j = 0; j < 6; j++){
            float4 a = row[lane + 32*j], c = us4[lane + 32*j];
            s += a.x*c.x + a.y*c.y + a.z*c.z + a.w*c.w;
        }
        s = warp_sum(s);
        if (!lane) sc[si] = s;
    }
    __syncthreads();
    // softmax over 256
    float v = sc[tid];
    float m = v;
    #pragma unroll
    for (int o = 16; o; o >>= 1) m = fmaxf(m, __shfl_xor_sync(0xffffffffu, m, o));
    if (!lane) red[w] = m;
    __syncthreads();
    if (tid == 0){
        float mm = red[0];
        for (int i = 1; i < 8; i++) mm = fmaxf(mm, red[i]);
        red[8] = mm;
    }
    __syncthreads();
    m = red[8];
    float e = expf(v - m);
    float z = warp_sum(e);
    if (!lane) red[w] = z;
    __syncthreads();
    if (tid == 0){
        float zz = 0.f;
        for (int i = 0; i < 8; i++) zz += red[i];
        red[8] = zz;
    }
    __syncthreads();
    sc[tid] = e / red[8];
    __syncthreads();
    // g[b,d] = sum_s w_s * feat_2d[b,s,d]
    float acc0 = 0.f, acc1 = 0.f, acc2 = 0.f;
    for (int si = 0; si < SS; si++){
        float wv = sc[si];
        const float* row = f2d + (b*SS + si)*D2D;
        acc0 += wv * row[tid];
        acc1 += wv * row[tid + 256];
        acc2 += wv * row[tid + 512];
    }
    g_g[b*D2D + tid]       = acc0;
    g_g[b*D2D + tid + 256] = acc1;
    g_g[b*D2D + tid + 512] = acc2;
}

// ---------------- K4: pooled_2d[b,p] = g[b,:].W2d[p,:] + b2d[p] ----------------
__global__ void k4_p2d(const float* __restrict__ W2, const float* __restrict__ b2){
    int b = blockIdx.x / 12, pt = blockIdx.x % 12;
    int p0 = pt * 256;
    __shared__ float gs[D2D];
    int tid = threadIdx.x, w = tid >> 5, lane = tid & 31;
    for (int d = tid; d < D2D; d += 256) gs[d] = g_g[b*D2D + d];
    __syncthreads();
    const float4* gs4 = (const float4*)gs;
    for (int i = 0; i < 32; i++){
        int p = p0 + w*32 + i;
        const float4* row = (const float4*)(W2 + p*D2D);
        float s = 0.f;
        #pragma unroll
        for (int j = 0; j < 6; j++){
            float4 a = row[lane + 32*j], c = gs4[lane + 32*j];
            s += a.x*c.x + a.y*c.y + a.z*c.z + a.w*c.w;
        }
        s = warp_sum(s);
        if (!lane) g_p2d[b*PP + p] = s + b2[p];
    }
}

// ---- K5: text split pooling: scores, partial softmax, unnormalized pooled ----
__global__ void k5_text(const float* __restrict__ ft){
    int b = blockIdx.x >> 3, ks = blockIdx.x & 7;
    int t0 = ks * 64;
    __shared__ float qs[DT];
    __shared__ float es[64];
    int tid = threadIdx.x, w = tid >> 5, lane = tid & 31;
    for (int i = tid; i < DT; i += 256) qs[i] = g_f3p[b*PP + i];
    __syncthreads();
    const float4* qs4 = (const float4*)qs;
    for (int i = 0; i < 8; i++){
        int t = w*8 + i;
        const float4* row = (const float4*)(ft + (b*TT + t0 + t)*DT);
        float s = 0.f;
        #pragma unroll
        for (int j = 0; j < 24; j++){
            float4 a = row[lane + 32*j], c = qs4[lane + 32*j];
            s += a.x*c.x + a.y*c.y + a.z*c.z + a.w*c.w;
        }
        s = warp_sum(s);
        if (!lane) es[t] = s;
    }
    __syncthreads();
    float m = -1e30f;
    #pragma unroll 8
    for (int i = 0; i < 64; i++) m = fmaxf(m, es[i]);
    __syncthreads();
    if (tid < 64) es[tid] = expf(es[tid] - m);
    __syncthreads();
    if (tid == 0){
        float z = 0.f;
        for (int i = 0; i < 64; i++) z += es[i];
        g_mpart[b*TS + ks] = m;
        g_zpart[b*TS + ks] = z;
    }
    float4 a0 = {0,0,0,0}, a1 = {0,0,0,0}, a2 = {0,0,0,0};
    for (int t = 0; t < 64; t++){
        float wv = es[t];
        const float4* row = (const float4*)(ft + (b*TT + t0 + t)*DT);
        float4 v0 = row[tid], v1 = row[tid + 256], v2 = row[tid + 512];
        a0.x += wv*v0.x; a0.y += wv*v0.y; a0.z += wv*v0.z; a0.w += wv*v0.w;
        a1.x += wv*v1.x; a1.y += wv*v1.y; a1.z += wv*v1.z; a1.w += wv*v1.w;
        a2.x += wv*v2.x; a2.y += wv*v2.y; a2.z += wv*v2.z; a2.w += wv*v2.w;
    }
    float4* vp4 = (float4*)g_vpart;
    int base = (b*TS + ks) * (PP/4);
    vp4[base + tid]       = a0;
    vp4[base + tid + 256] = a1;
    vp4[base + tid + 512] = a2;
}

// ---------------- K6: combine text partials ----------------
__global__ void k6_comb(void){
    int b = blockIdx.x, tid = threadIdx.x;
    float mv[TS], co[TS];
    float m = -1e30f;
    #pragma unroll
    for (int i = 0; i < TS; i++){ mv[i] = g_mpart[b*TS + i]; m = fmaxf(m, mv[i]); }
    float zt = 0.f;
    #pragma unroll
    for (int i = 0; i < TS; i++){ co[i] = expf(mv[i] - m); zt += co[i] * g_zpart[b*TS + i]; }
    float inv = 1.f / zt;
    const float4* vp4 = (const float4*)g_vpart;
    float4* pt4 = (float4*)g_ptext;
    #pragma unroll
    for (int j = 0; j < 3; j++){
        int p4 = tid + 256*j;
        float4 s = {0,0,0,0};
        #pragma unroll
        for (int i = 0; i < TS; i++){
            float4 v = vp4[(b*TS + i)*(PP/4) + p4];
            s.x += co[i]*v.x; s.y += co[i]*v.y; s.z += co[i]*v.z; s.w += co[i]*v.w;
        }
        s.x *= inv; s.y *= inv; s.z *= inv; s.w *= inv;
        pt4[b*(PP/4) + p4] = s;
    }
}

// ---------------- Kx: build x = concat(f3p, pooled_2d, pooled_text) ----------------
__global__ void kx_build(void){
    int e4 = blockIdx.x * 256 + threadIdx.x;          // float4 index, 73728 total
    int b = e4 / (XK/4);
    int k4 = e4 % (XK/4);
    const float4* src;
    if (k4 < PP/4)            src = (const float4*)g_f3p   + b*(PP/4) + k4;
    else if (k4 < 2*(PP/4))   src = (const float4*)g_p2d   + b*(PP/4) + (k4 - PP/4);
    else                      src = (const float4*)g_ptext + b*(PP/4) + (k4 - 2*(PP/4));
    ((float4*)g_x)[e4] = *src;
}

// ---------------- K7: fused GEMM partials  [32,9216] @ Wf^T ----------------
__global__ void __launch_bounds__(128) k7_fused(const float* __restrict__ Wf){
    int pt = blockIdx.x % 12, ks = blockIdx.x / 12;
    int p0 = pt * 256, k0 = ks * 384;
    __shared__ float xs[16*32];
    __shared__ float ws[16*260];
    int tid = threadIdx.x;
    int bg = tid & 3, pg = tid >> 2;     // bg<4, pg<32
    int b0 = bg * 8, pp0 = pg * 8;
    float acc[8][8];
    #pragma unroll
    for (int i = 0; i < 8; i++)
        #pragma unroll
        for (int j = 0; j < 8; j++) acc[i][j] = 0.f;

    for (int kk = k0; kk < k0 + 384; kk += 16){
        // stage x tile [16k x 32b] transposed
        {
            int bb = tid >> 2, kq = (tid & 3) * 4;
            float4 v = *(const float4*)&g_x[bb*XK + kk + kq];
            xs[(kq+0)*32 + bb] = v.x;
            xs[(kq+1)*32 + bb] = v.y;
            xs[(kq+2)*32 + bb] = v.z;
            xs[(kq+3)*32 + bb] = v.w;
        }
        // stage Wf tile [256p x 16k] -> ws[k][p]
        {
            int c = tid & 3, r0 = tid >> 2;
            #pragma unroll
            for (int i = 0; i < 8; i++){
                int r = r0 + i*32;
                float4 v = *(const float4*)&Wf[(p0 + r)*XK + kk + c*4];
                ws[(c*4+0)*260 + r] = v.x;
                ws[(c*4+1)*260 + r] = v.y;
                ws[(c*4+2)*260 + r] = v.z;
                ws[(c*4+3)*260 + r] = v.w;
            }
        }
        __syncthreads();
        #pragma unroll
        for (int k = 0; k < 16; k++){
            float4 xa = *(const float4*)&xs[k*32 + b0];
            float4 xb = *(const float4*)&xs[k*32 + b0 + 4];
            float4 wa = *(const float4*)&ws[k*260 + pp0];
            float4 wb = *(const float4*)&ws[k*260 + pp0 + 4];
            float xv[8] = {xa.x, xa.y, xa.z, xa.w, xb.x, xb.y, xb.z, xb.w};
            float wv[8] = {wa.x, wa.y, wa.z, wa.w, wb.x, wb.y, wb.z, wb.w};
            #pragma unroll
            for (int i = 0; i < 8; i++)
                #pragma unroll
                for (int j = 0; j < 8; j++)
                    acc[i][j] += xv[i] * wv[j];
        }
        __syncthreads();
    }
    #pragma unroll
    for (int i = 0; i < 8; i++){
        int b = b0 + i;
        float* dst = &g_fpart[(ks*BB + b)*PP + p0 + pp0];
        *(float4*)(dst)     = make_float4(acc[i][0], acc[i][1], acc[i][2], acc[i][3]);
        *(float4*)(dst + 4) = make_float4(acc[i][4], acc[i][5], acc[i][6], acc[i][7]);
    }
}

// ---------------- K8: reduce partials + bias, broadcast over SEQ ----------------
__global__ void k8_out(const float* __restrict__ bf, float* __restrict__ out){
    int bx = blockIdx.x;
    int b = bx / 12;
    int rem = bx % 12;
    int pt = rem >> 2, ss = rem & 3;
    int tid = threadIdx.x;
    int p = pt*1024 + tid*4;
    float4 v = *(const float4*)&bf[p];
    for (int ksv = 0; ksv < KS7; ksv++){
        float4 a = *(const float4*)&g_fpart[(ksv*BB + b)*PP + p];
        v.x += a.x; v.y += a.y; v.z += a.z; v.w += a.w;
    }
    long base = ((long)b*SEQ + ss*64)*PP + p;
    #pragma unroll 4
    for (int s = 0; s < 64; s++)
        *(float4*)&out[base + (long)s*PP] = v;
}

extern "C" void kernel_launch(void* const* d_in, const int* in_sizes, int n_in,
                              void* d_out, int out_size){
    const float* f3  = (const float*)d_in[0];
    const float* f2  = (const float*)d_in[1];
    const float* ftx = (const float*)d_in[2];
    const float* W3  = (const float*)d_in[3];
    const float* b3  = (const float*)d_in[4];
    const float* W2  = (const float*)d_in[5];
    const float* b2  = (const float*)d_in[6];
    const float* Wf  = (const float*)d_in[7];
    const float* bf  = (const float*)d_in[8];
    float* out = (float*)d_out;

    k1_f3p <<<384, 256>>>(f3, W3, b3);
    k2_u   <<<144, 256>>>(W2);
    k5_text<<<256, 256>>>(ftx);
    k3_s2d <<<32,  256>>>(f2);
    k4_p2d <<<384, 256>>>(W2, b2);
    k6_comb<<<32,  256>>>();
    kx_build<<<288, 256>>>();
    k7_fused<<<288, 128>>>(Wf);
    k8_out <<<384, 256>>>(bf, out);
}

// round 2
// speedup vs baseline: 1.2312x; 1.2312x over previous
#include <cuda_runtime.h>

#define BB   32
#define D3D  256
#define D2D  768
#define DT   3072
#define PP   3072
#define SS   256
#define TT   512
#define SEQ  256
#define XK   (PP*3)     // 9216

#define KS2  48         // k-split for u (p-chunks of 64)
#define SC2  8          // 2D s-splits (chunk 32)
#define TS   16         // text splits per batch (chunk 32)
#define KS7  24         // k-split for fused GEMM (k-chunk 384)

// ---- scratch (static device memory; no allocation) ----
__device__ float g_f3p[BB*PP];              // [32,3072]
__device__ float g_upart[KS2*BB*D2D];       // partial u
__device__ float g_u[BB*D2D];               // reduced u
__device__ float g_m2[BB*SC2];
__device__ float g_z2[BB*SC2];
__device__ float g_v2[BB*SC2*D2D];          // unnormalized 2D pooled partials
__device__ float g_g[BB*D2D];               // weighted feat_2d sum
__device__ float g_p2d[BB*PP];              // pooled_2d
__device__ float g_mpart[BB*TS];
__device__ float g_zpart[BB*TS];
__device__ float g_vpart[BB*TS*PP];         // unnormalized text pooled partials
__device__ float g_ptext[BB*PP];            // pooled_text
__device__ float g_x[BB*XK];                // concat input to fused GEMM
__device__ float g_fpart[KS7*BB*PP];        // fused GEMM partials

__device__ __forceinline__ float warp_sum(float v){
    #pragma unroll
    for (int o = 16; o; o >>= 1) v += __shfl_xor_sync(0xffffffffu, v, o);
    return v;
}

// ---------------- K1: f3p = feat_3d @ W3d^T + b3d  [32,3072] ----------------
__global__ void k1_f3p(const float* __restrict__ f3, const float* __restrict__ W3,
                       const float* __restrict__ b3){
    int b = blockIdx.x / 12, pt = blockIdx.x % 12;
    int p0 = pt * 256;
    __shared__ float fs[D3D];
    int tid = threadIdx.x, w = tid >> 5, lane = tid & 31;
    fs[tid] = f3[b*D3D + tid];
    __syncthreads();
    const float4* fs4 = (const float4*)fs;
    for (int i = 0; i < 32; i++){
        int p = p0 + w*32 + i;
        const float4* row = (const float4*)(W3 + p*D3D);
        float s = 0.f;
        #pragma unroll
        for (int j = 0; j < 2; j++){
            float4 a = row[lane + 32*j], c = fs4[lane + 32*j];
            s += a.x*c.x + a.y*c.y + a.z*c.z + a.w*c.w;
        }
        s = warp_sum(s);
        if (!lane) g_f3p[b*PP + p] = s + b3[p];
    }
}

// ---------------- K2: u[b,d] = sum_p f3p[b,p]*W2d[p,d] (partials) ----------------
__global__ void k2_u(const float* __restrict__ W2){
    int dt = blockIdx.x % 3, ks = blockIdx.x / 3;
    int tid = threadIdx.x;
    int d = dt*256 + tid;
    int pbase = ks * 64;
    __shared__ float fs[BB*64];   // [b][pp]
    for (int e = tid; e < BB*64; e += 256){
        int bb = e >> 6, pp = e & 63;
        fs[e] = g_f3p[bb*PP + pbase + pp];
    }
    __syncthreads();
    float acc[BB];
    #pragma unroll
    for (int bb = 0; bb < BB; bb++) acc[bb] = 0.f;
    const float4* fs4 = (const float4*)fs;
    for (int pp = 0; pp < 64; pp += 4){
        float w0 = W2[(pbase+pp+0)*D2D + d];
        float w1 = W2[(pbase+pp+1)*D2D + d];
        float w2 = W2[(pbase+pp+2)*D2D + d];
        float w3 = W2[(pbase+pp+3)*D2D + d];
        #pragma unroll
        for (int bb = 0; bb < BB; bb++){
            float4 f = fs4[bb*16 + (pp >> 2)];
            acc[bb] += f.x*w0 + f.y*w1 + f.z*w2 + f.w*w3;
        }
    }
    #pragma unroll
    for (int bb = 0; bb < BB; bb++)
        g_upart[(ks*BB + bb)*D2D + d] = acc[bb];
}

// ---------------- K2b: reduce g_upart -> g_u ----------------
__global__ void k_ured(void){
    int e = blockIdx.x * 256 + threadIdx.x;   // float4 index, 6144 total
    const float4* up = (const float4*)g_upart;
    float4 s = {0,0,0,0};
    #pragma unroll 8
    for (int ks = 0; ks < KS2; ks++){
        float4 v = up[ks*(BB*D2D/4) + e];
        s.x += v.x; s.y += v.y; s.z += v.z; s.w += v.w;
    }
    ((float4*)g_u)[e] = s;
}

// ---- K3a: 2D split pooling: scores chunk, partial softmax, unnormalized pooled ----
__global__ void k3a_s2d(const float* __restrict__ f2d){
    int b = blockIdx.x >> 3, cs = blockIdx.x & 7;
    int s0 = cs * 32;
    __shared__ float us[D2D];
    __shared__ float es[32];
    int tid = threadIdx.x, w = tid >> 5, lane = tid & 31;
    for (int d = tid; d < D2D; d += 256) us[d] = g_u[b*D2D + d];
    __syncthreads();
    const float4* us4 = (const float4*)us;
    #pragma unroll
    for (int i = 0; i < 4; i++){
        int si = w*4 + i;
        const float4* row = (const float4*)(f2d + (b*SS + s0 + si)*D2D);
        float s = 0.f;
        #pragma unroll
        for (int j = 0; j < 6; j++){
            float4 a = row[lane + 32*j], c = us4[lane + 32*j];
            s += a.x*c.x + a.y*c.y + a.z*c.z + a.w*c.w;
        }
        s = warp_sum(s);
        if (!lane) es[si] = s;
    }
    __syncthreads();
    float m = -1e30f;
    #pragma unroll
    for (int i = 0; i < 32; i++) m = fmaxf(m, es[i]);
    __syncthreads();
    if (tid < 32) es[tid] = expf(es[tid] - m);
    __syncthreads();
    if (tid == 0){
        float z = 0.f;
        #pragma unroll
        for (int i = 0; i < 32; i++) z += es[i];
        g_m2[b*SC2 + cs] = m;
        g_z2[b*SC2 + cs] = z;
    }
    if (tid < 192){
        float4 acc = {0,0,0,0};
        #pragma unroll 4
        for (int t = 0; t < 32; t++){
            float wv = es[t];
            float4 v = ((const float4*)(f2d + (b*SS + s0 + t)*D2D))[tid];
            acc.x += wv*v.x; acc.y += wv*v.y; acc.z += wv*v.z; acc.w += wv*v.w;
        }
        ((float4*)g_v2)[(b*SC2 + cs)*(D2D/4) + tid] = acc;
    }
}

// ---------------- K3b: combine 2D partials -> g_g ----------------
__global__ void k3b_comb(void){
    int b = blockIdx.x, tid = threadIdx.x;
    float mv[SC2], co[SC2];
    float m = -1e30f;
    #pragma unroll
    for (int i = 0; i < SC2; i++){ mv[i] = g_m2[b*SC2 + i]; m = fmaxf(m, mv[i]); }
    float zt = 0.f;
    #pragma unroll
    for (int i = 0; i < SC2; i++){ co[i] = expf(mv[i] - m); zt += co[i] * g_z2[b*SC2 + i]; }
    float inv = 1.f / zt;
    if (tid < 192){
        float4 s = {0,0,0,0};
        #pragma unroll
        for (int i = 0; i < SC2; i++){
            float4 v = ((const float4*)g_v2)[(b*SC2 + i)*(D2D/4) + tid];
            s.x += co[i]*v.x; s.y += co[i]*v.y; s.z += co[i]*v.z; s.w += co[i]*v.w;
        }
        s.x *= inv; s.y *= inv; s.z *= inv; s.w *= inv;
        ((float4*)g_g)[b*(D2D/4) + tid] = s;
    }
}

// ---------------- K4: pooled_2d[b,p] = g[b,:].W2d[p,:] + b2d[p] ----------------
__global__ void k4_p2d(const float* __restrict__ W2, const float* __restrict__ b2){
    int b = blockIdx.x / 12, pt = blockIdx.x % 12;
    int p0 = pt * 256;
    __shared__ float gs[D2D];
    int tid = threadIdx.x, w = tid >> 5, lane = tid & 31;
    for (int d = tid; d < D2D; d += 256) gs[d] = g_g[b*D2D + d];
    __syncthreads();
    const float4* gs4 = (const float4*)gs;
    for (int i = 0; i < 32; i++){
        int p = p0 + w*32 + i;
        const float4* row = (const float4*)(W2 + p*D2D);
        float s = 0.f;
        #pragma unroll
        for (int j = 0; j < 6; j++){
            float4 a = row[lane + 32*j], c = gs4[lane + 32*j];
            s += a.x*c.x + a.y*c.y + a.z*c.z + a.w*c.w;
        }
        s = warp_sum(s);
        if (!lane) g_p2d[b*PP + p] = s + b2[p];
    }
}

// ---- K5: text split pooling: scores, partial softmax, unnormalized pooled ----
__global__ void k5_text(const float* __restrict__ ft){
    int b = blockIdx.x >> 4, ks = blockIdx.x & 15;
    int t0 = ks * 32;
    __shared__ float qs[DT];
    __shared__ float es[32];
    int tid = threadIdx.x, w = tid >> 5, lane = tid & 31;
    for (int i = tid; i < DT; i += 256) qs[i] = g_f3p[b*PP + i];
    __syncthreads();
    const float4* qs4 = (const float4*)qs;
    #pragma unroll
    for (int i = 0; i < 4; i++){
        int t = w*4 + i;
        const float4* row = (const float4*)(ft + (b*TT + t0 + t)*DT);
        float s = 0.f;
        #pragma unroll
        for (int j = 0; j < 24; j++){
            float4 a = row[lane + 32*j], c = qs4[lane + 32*j];
            s += a.x*c.x + a.y*c.y + a.z*c.z + a.w*c.w;
        }
        s = warp_sum(s);
        if (!lane) es[t] = s;
    }
    __syncthreads();
    float m = -1e30f;
    #pragma unroll
    for (int i = 0; i < 32; i++) m = fmaxf(m, es[i]);
    __syncthreads();
    if (tid < 32) es[tid] = expf(es[tid] - m);
    __syncthreads();
    if (tid == 0){
        float z = 0.f;
        #pragma unroll
        for (int i = 0; i < 32; i++) z += es[i];
        g_mpart[b*TS + ks] = m;
        g_zpart[b*TS + ks] = z;
    }
    float4 a0 = {0,0,0,0}, a1 = {0,0,0,0}, a2 = {0,0,0,0};
    #pragma unroll 2
    for (int t = 0; t < 32; t++){
        float wv = es[t];
        const float4* row = (const float4*)(ft + (b*TT + t0 + t)*DT);
        float4 v0 = row[tid], v1 = row[tid + 256], v2 = row[tid + 512];
        a0.x += wv*v0.x; a0.y += wv*v0.y; a0.z += wv*v0.z; a0.w += wv*v0.w;
        a1.x += wv*v1.x; a1.y += wv*v1.y; a1.z += wv*v1.z; a1.w += wv*v1.w;
        a2.x += wv*v2.x; a2.y += wv*v2.y; a2.z += wv*v2.z; a2.w += wv*v2.w;
    }
    float4* vp4 = (float4*)g_vpart;
    int base = (b*TS + ks) * (PP/4);
    vp4[base + tid]       = a0;
    vp4[base + tid + 256] = a1;
    vp4[base + tid + 512] = a2;
}

// ---------------- K6: combine text partials ----------------
__global__ void k6_comb(void){
    int b = blockIdx.x, tid = threadIdx.x;
    float mv[TS], co[TS];
    float m = -1e30f;
    #pragma unroll
    for (int i = 0; i < TS; i++){ mv[i] = g_mpart[b*TS + i]; m = fmaxf(m, mv[i]); }
    float zt = 0.f;
    #pragma unroll
    for (int i = 0; i < TS; i++){ co[i] = expf(mv[i] - m); zt += co[i] * g_zpart[b*TS + i]; }
    float inv = 1.f / zt;
    const float4* vp4 = (const float4*)g_vpart;
    float4* pt4 = (float4*)g_ptext;
    #pragma unroll
    for (int j = 0; j < 3; j++){
        int p4 = tid + 256*j;
        float4 s = {0,0,0,0};
        #pragma unroll
        for (int i = 0; i < TS; i++){
            float4 v = vp4[(b*TS + i)*(PP/4) + p4];
            s.x += co[i]*v.x; s.y += co[i]*v.y; s.z += co[i]*v.z; s.w += co[i]*v.w;
        }
        s.x *= inv; s.y *= inv; s.z *= inv; s.w *= inv;
        pt4[b*(PP/4) + p4] = s;
    }
}

// ---------------- Kx: build x = concat(f3p, pooled_2d, pooled_text) ----------------
__global__ void kx_build(void){
    int e4 = blockIdx.x * 256 + threadIdx.x;          // float4 index, 73728 total
    int b = e4 / (XK/4);
    int k4 = e4 % (XK/4);
    const float4* src;
    if (k4 < PP/4)            src = (const float4*)g_f3p   + b*(PP/4) + k4;
    else if (k4 < 2*(PP/4))   src = (const float4*)g_p2d   + b*(PP/4) + (k4 - PP/4);
    else                      src = (const float4*)g_ptext + b*(PP/4) + (k4 - 2*(PP/4));
    ((float4*)g_x)[e4] = *src;
}

// ---------------- K7: fused GEMM partials  [32,9216] @ Wf^T ----------------
__global__ void __launch_bounds__(128) k7_fused(const float* __restrict__ Wf){
    int pt = blockIdx.x % 12, ks = blockIdx.x / 12;
    int p0 = pt * 256, k0 = ks * 384;
    __shared__ float xs[16*32];
    __shared__ float ws[16*260];
    int tid = threadIdx.x;
    int bg = tid & 3, pg = tid >> 2;     // bg<4, pg<32
    int b0 = bg * 8, pp0 = pg * 8;
    float acc[8][8];
    #pragma unroll
    for (int i = 0; i < 8; i++)
        #pragma unroll
        for (int j = 0; j < 8; j++) acc[i][j] = 0.f;

    for (int kk = k0; kk < k0 + 384; kk += 16){
        {
            int bb = tid >> 2, kq = (tid & 3) * 4;
            float4 v = *(const float4*)&g_x[bb*XK + kk + kq];
            xs[(kq+0)*32 + bb] = v.x;
            xs[(kq+1)*32 + bb] = v.y;
            xs[(kq+2)*32 + bb] = v.z;
            xs[(kq+3)*32 + bb] = v.w;
        }
        {
            int c = tid & 3, r0 = tid >> 2;
            #pragma unroll
            for (int i = 0; i < 8; i++){
                int r = r0 + i*32;
                float4 v = *(const float4*)&Wf[(p0 + r)*XK + kk + c*4];
                ws[(c*4+0)*260 + r] = v.x;
                ws[(c*4+1)*260 + r] = v.y;
                ws[(c*4+2)*260 + r] = v.z;
                ws[(c*4+3)*260 + r] = v.w;
            }
        }
        __syncthreads();
        #pragma unroll
        for (int k = 0; k < 16; k++){
            float4 xa = *(const float4*)&xs[k*32 + b0];
            float4 xb = *(const float4*)&xs[k*32 + b0 + 4];
            float4 wa = *(const float4*)&ws[k*260 + pp0];
            float4 wb = *(const float4*)&ws[k*260 + pp0 + 4];
            float xv[8] = {xa.x, xa.y, xa.z, xa.w, xb.x, xb.y, xb.z, xb.w};
            float wv[8] = {wa.x, wa.y, wa.z, wa.w, wb.x, wb.y, wb.z, wb.w};
            #pragma unroll
            for (int i = 0; i < 8; i++)
                #pragma unroll
                for (int j = 0; j < 8; j++)
                    acc[i][j] += xv[i] * wv[j];
        }
        __syncthreads();
    }
    #pragma unroll
    for (int i = 0; i < 8; i++){
        int b = b0 + i;
        float* dst = &g_fpart[(ks*BB + b)*PP + p0 + pp0];
        *(float4*)(dst)     = make_float4(acc[i][0], acc[i][1], acc[i][2], acc[i][3]);
        *(float4*)(dst + 4) = make_float4(acc[i][4], acc[i][5], acc[i][6], acc[i][7]);
    }
}

// ---------------- K8: reduce partials + bias, broadcast over SEQ ----------------
__global__ void k8_out(const float* __restrict__ bf, float* __restrict__ out){
    int bx = blockIdx.x;
    int b = bx / 12;
    int rem = bx % 12;
    int pt = rem >> 2, ss = rem & 3;
    int tid = threadIdx.x;
    int p = pt*1024 + tid*4;
    float4 v = *(const float4*)&bf[p];
    for (int ksv = 0; ksv < KS7; ksv++){
        float4 a = *(const float4*)&g_fpart[(ksv*BB + b)*PP + p];
        v.x += a.x; v.y += a.y; v.z += a.z; v.w += a.w;
    }
    long base = ((long)b*SEQ + ss*64)*PP + p;
    #pragma unroll 4
    for (int s = 0; s < 64; s++)
        *(float4*)&out[base + (long)s*PP] = v;
}

extern "C" void kernel_launch(void* const* d_in, const int* in_sizes, int n_in,
                              void* d_out, int out_size){
    const float* f3  = (const float*)d_in[0];
    const float* f2  = (const float*)d_in[1];
    const float* ftx = (const float*)d_in[2];
    const float* W3  = (const float*)d_in[3];
    const float* b3  = (const float*)d_in[4];
    const float* W2  = (const float*)d_in[5];
    const float* b2  = (const float*)d_in[6];
    const float* Wf  = (const float*)d_in[7];
    const float* bf  = (const float*)d_in[8];
    float* out = (float*)d_out;

    static cudaStream_t s2 = nullptr;
    static cudaEvent_t ev1 = nullptr, ev2 = nullptr;
    if (!s2){
        cudaStreamCreateWithFlags(&s2, cudaStreamNonBlocking);
        cudaEventCreateWithFlags(&ev1, cudaEventDisableTiming);
        cudaEventCreateWithFlags(&ev2, cudaEventDisableTiming);
    }

    // stream 0: f3p
    k1_f3p <<<384, 256>>>(f3, W3, b3);
    cudaEventRecord(ev1, 0);

    // fork: text pooling on s2 (depends only on f3p)
    cudaStreamWaitEvent(s2, ev1, 0);
    k5_text<<<512, 256, 0, s2>>>(ftx);
    k6_comb<<<32,  256, 0, s2>>>();
    cudaEventRecord(ev2, s2);

    // stream 0: 2D pooling chain
    k2_u   <<<144, 256>>>(W2);
    k_ured <<<24,  256>>>();
    k3a_s2d<<<256, 256>>>(f2);
    k3b_comb<<<32, 256>>>();
    k4_p2d <<<384, 256>>>(W2, b2);

    // join, then fused GEMM + output
    cudaStreamWaitEvent(0, ev2, 0);
    kx_build<<<288, 256>>>();
    k7_fused<<<288, 128>>>(Wf);
    k8_out <<<384, 256>>>(bf, out);
}

// round 3
// speedup vs baseline: 1.2328x; 1.0013x over previous
#include <cuda_runtime.h>

#define BB   32
#define D3D  256
#define D2D  768
#define DT   3072
#define PP   3072
#define SS   256
#define TT   512
#define SEQ  256
#define XK   (PP*3)     // 9216

#define KS2  96         // k-split for u (p-chunks of 32)
#define SC2  8          // 2D s-splits (chunk 32)
#define TS   64         // text splits per batch (chunk 8)
#define KS7  48         // k-split for fused GEMM (k-chunk 192)

// ---- scratch (static device memory; no allocation) ----
__device__ float g_f3p[BB*PP];
__device__ float g_upart[KS2*BB*D2D];
__device__ float g_u[BB*D2D];
__device__ float g_m2[BB*SC2];
__device__ float g_z2[BB*SC2];
__device__ float g_v2[BB*SC2*D2D];
__device__ float g_g[BB*D2D];
__device__ float g_p2d[BB*PP];
__device__ float g_mpart[BB*TS];
__device__ float g_zpart[BB*TS];
__device__ float g_vpart[BB*TS*PP];         // 25.2 MB
__device__ float g_ptext[BB*PP];
__device__ float g_fpart[KS7*BB*PP];        // 18.9 MB
__device__ float g_fvec[BB*PP];

__device__ __forceinline__ float warp_sum(float v){
    #pragma unroll
    for (int o = 16; o; o >>= 1) v += __shfl_xor_sync(0xffffffffu, v, o);
    return v;
}

__device__ __forceinline__ void ffma2(unsigned long long& d, unsigned long long a,
                                      unsigned long long b){
    asm("fma.rn.f32x2 %0, %1, %2, %0;" : "+l"(d) : "l"(a), "l"(b));
}

// ---- K1: f3p = feat_3d @ W3d^T + b3d  (8 batches per block) ----
__global__ void k1_f3p(const float* __restrict__ f3, const float* __restrict__ W3,
                       const float* __restrict__ b3){
    int bg = blockIdx.x / 48, pt = blockIdx.x % 48;
    int p0 = pt * 64;
    __shared__ float fs[8*D3D];
    int tid = threadIdx.x, w = tid >> 5, lane = tid & 31;
    #pragma unroll
    for (int e = tid; e < 8*D3D; e += 256) fs[e] = f3[bg*8*D3D + e];
    __syncthreads();
    const float4* fs4 = (const float4*)fs;
    for (int i = 0; i < 8; i++){
        int p = p0 + w*8 + i;
        const float4* row = (const float4*)(W3 + p*D3D);
        float4 a0 = row[lane], a1 = row[lane+32];
        float acc[8];
        #pragma unroll
        for (int bb = 0; bb < 8; bb++){
            float4 c0 = fs4[bb*64 + lane], c1 = fs4[bb*64 + lane + 32];
            acc[bb] = a0.x*c0.x + a0.y*c0.y + a0.z*c0.z + a0.w*c0.w
                    + a1.x*c1.x + a1.y*c1.y + a1.z*c1.z + a1.w*c1.w;
        }
        #pragma unroll
        for (int bb = 0; bb < 8; bb++){
            float s = warp_sum(acc[bb]);
            if (!lane) g_f3p[(bg*8 + bb)*PP + p] = s + b3[p];
        }
    }
}

// ---- K2: u partials: u[b,d] = sum_p f3p[b,p]*W2d[p,d] ----
__global__ void k2_u(const float* __restrict__ W2){
    int dt = blockIdx.x % 3, ks = blockIdx.x / 3;
    int tid = threadIdx.x;
    int d = dt*256 + tid;
    int pbase = ks * 32;
    __shared__ float fs[BB*32];
    for (int e = tid; e < BB*32; e += 256){
        int bb = e >> 5, pp = e & 31;
        fs[e] = g_f3p[bb*PP + pbase + pp];
    }
    __syncthreads();
    float acc[BB];
    #pragma unroll
    for (int bb = 0; bb < BB; bb++) acc[bb] = 0.f;
    const float4* fs4 = (const float4*)fs;
    for (int pp = 0; pp < 32; pp += 4){
        float w0 = W2[(pbase+pp+0)*D2D + d];
        float w1 = W2[(pbase+pp+1)*D2D + d];
        float w2 = W2[(pbase+pp+2)*D2D + d];
        float w3 = W2[(pbase+pp+3)*D2D + d];
        #pragma unroll
        for (int bb = 0; bb < BB; bb++){
            float4 f = fs4[bb*8 + (pp >> 2)];
            acc[bb] += f.x*w0 + f.y*w1 + f.z*w2 + f.w*w3;
        }
    }
    #pragma unroll
    for (int bb = 0; bb < BB; bb++)
        g_upart[(ks*BB + bb)*D2D + d] = acc[bb];
}

// ---- K2b: reduce partials -> g_u ----
__global__ void k_ured(void){
    int e = blockIdx.x * 256 + threadIdx.x;   // 6144 float4
    const float4* up = (const float4*)g_upart;
    float4 s = {0,0,0,0};
    #pragma unroll 8
    for (int ks = 0; ks < KS2; ks++){
        float4 v = up[(size_t)ks*(BB*D2D/4) + e];
        s.x += v.x; s.y += v.y; s.z += v.z; s.w += v.w;
    }
    ((float4*)g_u)[e] = s;
}

// ---- K3a: 2D pooling, single DRAM pass via smem tile (32 rows) ----
__global__ void k3a_s2d(const float* __restrict__ f2d){
    extern __shared__ float sm3[];
    float* us = sm3;               // 768
    float* tile = sm3 + D2D;       // 32*768
    __shared__ float es[32];
    int b = blockIdx.x >> 3, cs = blockIdx.x & 7;
    int s0 = cs * 32;
    int tid = threadIdx.x, w = tid >> 5, lane = tid & 31;
    const float4* src = (const float4*)(f2d + ((size_t)(b*SS + s0))*D2D);
    float4* t4 = (float4*)tile;
    #pragma unroll
    for (int i = 0; i < 24; i++) t4[tid + 256*i] = src[tid + 256*i];
    if (tid < 192) ((float4*)us)[tid] = ((const float4*)(g_u + b*D2D))[tid];
    __syncthreads();
    const float4* us4 = (const float4*)us;
    #pragma unroll
    for (int i = 0; i < 4; i++){
        int si = w*4 + i;
        const float4* row = t4 + si*192;
        float s = 0.f;
        #pragma unroll
        for (int j = 0; j < 6; j++){
            float4 a = row[lane + 32*j], c = us4[lane + 32*j];
            s += a.x*c.x + a.y*c.y + a.z*c.z + a.w*c.w;
        }
        s = warp_sum(s);
        if (!lane) es[si] = s;
    }
    __syncthreads();
    float m = -1e30f;
    #pragma unroll
    for (int i = 0; i < 32; i++) m = fmaxf(m, es[i]);
    __syncthreads();
    if (tid < 32) es[tid] = expf(es[tid] - m);
    __syncthreads();
    if (tid == 0){
        float z = 0.f;
        #pragma unroll
        for (int i = 0; i < 32; i++) z += es[i];
        g_m2[b*SC2 + cs] = m;
        g_z2[b*SC2 + cs] = z;
    }
    if (tid < 192){
        float4 acc = {0,0,0,0};
        #pragma unroll 4
        for (int t = 0; t < 32; t++){
            float wv = es[t];
            float4 v = t4[t*192 + tid];
            acc.x += wv*v.x; acc.y += wv*v.y; acc.z += wv*v.z; acc.w += wv*v.w;
        }
        ((float4*)g_v2)[(b*SC2 + cs)*(D2D/4) + tid] = acc;
    }
}

// ---- K3b: combine 2D partials -> g_g ----
__global__ void k3b_comb(void){
    int b = blockIdx.x, tid = threadIdx.x;
    float mv[SC2], co[SC2];
    float m = -1e30f;
    #pragma unroll
    for (int i = 0; i < SC2; i++){ mv[i] = g_m2[b*SC2 + i]; m = fmaxf(m, mv[i]); }
    float zt = 0.f;
    #pragma unroll
    for (int i = 0; i < SC2; i++){ co[i] = expf(mv[i] - m); zt += co[i] * g_z2[b*SC2 + i]; }
    float inv = 1.f / zt;
    if (tid < 192){
        float4 s = {0,0,0,0};
        #pragma unroll
        for (int i = 0; i < SC2; i++){
            float4 v = ((const float4*)g_v2)[(b*SC2 + i)*(D2D/4) + tid];
            s.x += co[i]*v.x; s.y += co[i]*v.y; s.z += co[i]*v.z; s.w += co[i]*v.w;
        }
        s.x *= inv; s.y *= inv; s.z *= inv; s.w *= inv;
        ((float4*)g_g)[b*(D2D/4) + tid] = s;
    }
}

// ---- K4: pooled_2d = g @ W2^T + b2d  (8 batches per block) ----
__global__ void k4_p2d(const float* __restrict__ W2, const float* __restrict__ b2){
    int bg = blockIdx.x / 48, pt = blockIdx.x % 48;
    int p0 = pt * 64;
    __shared__ float gs[8*D2D];   // 24 KB
    int tid = threadIdx.x, w = tid >> 5, lane = tid & 31;
    #pragma unroll
    for (int e = tid; e < 8*D2D; e += 256) gs[e] = g_g[bg*8*D2D + e];
    __syncthreads();
    const float4* gs4 = (const float4*)gs;
    for (int i = 0; i < 8; i++){
        int p = p0 + w*8 + i;
        const float4* row = (const float4*)(W2 + p*D2D);
        float4 a[6];
        #pragma unroll
        for (int j = 0; j < 6; j++) a[j] = row[lane + 32*j];
        float acc[8];
        #pragma unroll
        for (int bb = 0; bb < 8; bb++){
            float s = 0.f;
            #pragma unroll
            for (int j = 0; j < 6; j++){
                float4 c = gs4[bb*192 + lane + 32*j];
                s += a[j].x*c.x + a[j].y*c.y + a[j].z*c.z + a[j].w*c.w;
            }
            acc[bb] = s;
        }
        #pragma unroll
        for (int bb = 0; bb < 8; bb++){
            float s = warp_sum(acc[bb]);
            if (!lane) g_p2d[(bg*8 + bb)*PP + p] = s + b2[p];
        }
    }
}

// ---- K5: text pooling, single DRAM pass via smem tile (8 rows) ----
__global__ void k5_text(const float* __restrict__ ft){
    extern __shared__ float sm5[];
    float* qs = sm5;               // 3072
    float* tile = sm5 + DT;        // 8*3072
    __shared__ float es[8];
    int b = blockIdx.x >> 6, ks = blockIdx.x & 63;
    int t0 = ks * 8;
    int tid = threadIdx.x, w = tid >> 5, lane = tid & 31;
    const float4* src = (const float4*)(ft + ((size_t)(b*TT + t0))*DT);
    float4* t4 = (float4*)tile;
    #pragma unroll
    for (int i = 0; i < 24; i++) t4[tid + 256*i] = src[tid + 256*i];
    float4* q4 = (float4*)qs;
    const float4* q4g = (const float4*)(g_f3p + b*PP);
    #pragma unroll
    for (int i = 0; i < 3; i++) q4[tid + 256*i] = q4g[tid + 256*i];
    __syncthreads();
    {
        const float4* row = t4 + w*768;
        float s = 0.f;
        #pragma unroll
        for (int j = 0; j < 24; j++){
            float4 a = row[lane + 32*j], c = q4[lane + 32*j];
            s += a.x*c.x + a.y*c.y + a.z*c.z + a.w*c.w;
        }
        s = warp_sum(s);
        if (!lane) es[w] = s;
    }
    __syncthreads();
    float m = -1e30f;
    #pragma unroll
    for (int i = 0; i < 8; i++) m = fmaxf(m, es[i]);
    __syncthreads();
    if (tid < 8) es[tid] = expf(es[tid] - m);
    __syncthreads();
    if (tid == 0){
        float z = 0.f;
        #pragma unroll
        for (int i = 0; i < 8; i++) z += es[i];
        g_mpart[b*TS + ks] = m;
        g_zpart[b*TS + ks] = z;
    }
    float4 a0 = {0,0,0,0}, a1 = {0,0,0,0}, a2 = {0,0,0,0};
    #pragma unroll
    for (int t = 0; t < 8; t++){
        float wv = es[t];
        float4 v0 = t4[t*768 + tid], v1 = t4[t*768 + tid + 256], v2 = t4[t*768 + tid + 512];
        a0.x += wv*v0.x; a0.y += wv*v0.y; a0.z += wv*v0.z; a0.w += wv*v0.w;
        a1.x += wv*v1.x; a1.y += wv*v1.y; a1.z += wv*v1.z; a1.w += wv*v1.w;
        a2.x += wv*v2.x; a2.y += wv*v2.y; a2.z += wv*v2.z; a2.w += wv*v2.w;
    }
    float4* vp4 = (float4*)g_vpart;
    size_t base = (size_t)(b*TS + ks) * (PP/4);
    vp4[base + tid]       = a0;
    vp4[base + tid + 256] = a1;
    vp4[base + tid + 512] = a2;
}

// ---- K6: combine text partials ----
__global__ void k6_comb(void){
    int b = blockIdx.x / 3, ct = blockIdx.x % 3;
    int tid = threadIdx.x;
    __shared__ float ms[TS], co[TS], zs[TS];
    __shared__ float zred;
    if (tid < TS) ms[tid] = g_mpart[b*TS + tid];
    __syncthreads();
    float m = -1e30f;
    #pragma unroll
    for (int i = 0; i < TS; i++) m = fmaxf(m, ms[i]);
    if (tid < TS){
        float c = expf(ms[tid] - m);
        co[tid] = c;
        zs[tid] = c * g_zpart[b*TS + tid];
    }
    __syncthreads();
    if (tid == 0){
        float z = 0.f;
        #pragma unroll
        for (int i = 0; i < TS; i++) z += zs[i];
        zred = z;
    }
    __syncthreads();
    float inv = 1.f / zred;
    int p4 = ct*256 + tid;
    float4 s = {0,0,0,0};
    #pragma unroll 4
    for (int i = 0; i < TS; i++){
        float c = co[i];
        float4 v = ((const float4*)g_vpart)[(size_t)(b*TS + i)*(PP/4) + p4];
        s.x += c*v.x; s.y += c*v.y; s.z += c*v.z; s.w += c*v.w;
    }
    s.x *= inv; s.y *= inv; s.z *= inv; s.w *= inv;
    ((float4*)g_ptext)[b*(PP/4) + p4] = s;
}

// ---- K7: fused GEMM partials via FFMA2 (f32x2), x sourced in-place ----
__global__ void __launch_bounds__(256) k7_fused(const float* __restrict__ Wf){
    int pt = blockIdx.x % 12, ks = blockIdx.x / 12;
    int p0 = pt * 256, k0 = ks * 192;
    const float* xsrc = (k0 < PP) ? g_f3p : (k0 < 2*PP) ? g_p2d : g_ptext;
    int koff = k0 % PP;
    __shared__ float xs[16*32];
    __shared__ float ws2[16*520];    // duplicated w: ws2[k][2p+{0,1}]
    int tid = threadIdx.x;
    int pg = tid & 63, bg = tid >> 6;
    int b0 = bg * 8, pp0 = pg * 4;
    unsigned long long acc[4][4];
    #pragma unroll
    for (int i = 0; i < 4; i++)
        #pragma unroll
        for (int j = 0; j < 4; j++) acc[i][j] = 0ull;

    for (int kt = 0; kt < 192; kt += 16){
        if (tid < 128){
            int bb = tid >> 2, kq = (tid & 3) * 4;
            float4 v = *(const float4*)&xsrc[bb*PP + koff + kt + kq];
            xs[(kq+0)*32 + bb] = v.x;
            xs[(kq+1)*32 + bb] = v.y;
            xs[(kq+2)*32 + bb] = v.z;
            xs[(kq+3)*32 + bb] = v.w;
        }
        {
            int c = tid & 3, r0 = tid >> 2;
            #pragma unroll
            for (int i = 0; i < 4; i++){
                int r = r0 + i*64;
                float4 v = *(const float4*)&Wf[(size_t)(p0 + r)*XK + k0 + kt + c*4];
                *(float2*)&ws2[(c*4+0)*520 + 2*r] = make_float2(v.x, v.x);
                *(float2*)&ws2[(c*4+1)*520 + 2*r] = make_float2(v.y, v.y);
                *(float2*)&ws2[(c*4+2)*520 + 2*r] = make_float2(v.z, v.z);
                *(float2*)&ws2[(c*4+3)*520 + 2*r] = make_float2(v.w, v.w);
            }
        }
        __syncthreads();
        #pragma unroll
        for (int k = 0; k < 16; k++){
            ulonglong2 xa = *(const ulonglong2*)&xs[k*32 + b0];      // b pairs 0,1
            ulonglong2 xb = *(const ulonglong2*)&xs[k*32 + b0 + 4];  // b pairs 2,3
            ulonglong2 wa = *(const ulonglong2*)&ws2[k*520 + 2*pp0];     // (w0,w0),(w1,w1)
            ulonglong2 wb = *(const ulonglong2*)&ws2[k*520 + 2*pp0 + 4]; // (w2,w2),(w3,w3)
            unsigned long long xp[4] = {xa.x, xa.y, xb.x, xb.y};
            unsigned long long wp[4] = {wa.x, wa.y, wb.x, wb.y};
            #pragma unroll
            for (int i = 0; i < 4; i++)
                #pragma unroll
                for (int j = 0; j < 4; j++)
                    ffma2(acc[i][j], xp[i], wp[j]);
        }
        __syncthreads();
    }
    #pragma unroll
    for (int i = 0; i < 4; i++){
        #pragma unroll
        for (int q = 0; q < 2; q++){
            int b = b0 + 2*i + q;
            float4 r;
            float* rp = (float*)&r;
            #pragma unroll
            for (int j = 0; j < 4; j++){
                unsigned long long v = acc[i][j];
                unsigned int bits = q ? (unsigned int)(v >> 32) : (unsigned int)(v & 0xffffffffu);
                rp[j] = __uint_as_float(bits);
            }
            *(float4*)&g_fpart[(size_t)(ks*BB + b)*PP + p0 + pp0] = r;
        }
    }
}

// ---- K8a: reduce fused partials + bias -> fvec ----
__global__ void k8a_red(const float* __restrict__ bf){
    int e = blockIdx.x * 256 + threadIdx.x;   // 24576 float4
    int b = e / (PP/4), p4 = e % (PP/4);
    float4 v = ((const float4*)bf)[p4];
    const float4* fp4 = (const float4*)g_fpart;
    #pragma unroll 8
    for (int ks = 0; ks < KS7; ks++){
        float4 a = fp4[(size_t)(ks*BB + b)*(PP/4) + p4];
        v.x += a.x; v.y += a.y; v.z += a.z; v.w += a.w;
    }
    ((float4*)g_fvec)[e] = v;
}

// ---- K8b: broadcast over SEQ ----
__global__ void k8b_out(float* __restrict__ out){
    int bx = blockIdx.x;
    int b = bx / 12;
    int rem = bx % 12;
    int pt = rem >> 2, ss = rem & 3;
    int tid = threadIdx.x;
    int p4 = pt*256 + tid;
    float4 v = ((const float4*)g_fvec)[b*(PP/4) + p4];
    size_t base = ((size_t)b*SEQ + ss*64)*PP;
    float4* o4 = (float4*)(out + base);
    #pragma unroll 4
    for (int s = 0; s < 64; s++)
        o4[(size_t)s*(PP/4) + p4] = v;
}

extern "C" void kernel_launch(void* const* d_in, const int* in_sizes, int n_in,
                              void* d_out, int out_size){
    const float* f3  = (const float*)d_in[0];
    const float* f2  = (const float*)d_in[1];
    const float* ftx = (const float*)d_in[2];
    const float* W3  = (const float*)d_in[3];
    const float* b3  = (const float*)d_in[4];
    const float* W2  = (const float*)d_in[5];
    const float* b2  = (const float*)d_in[6];
    const float* Wf  = (const float*)d_in[7];
    const float* bf  = (const float*)d_in[8];
    float* out = (float*)d_out;

    static cudaStream_t s2 = nullptr;
    static cudaEvent_t ev1 = nullptr, ev2 = nullptr;
    if (!s2){
        cudaStreamCreateWithFlags(&s2, cudaStreamNonBlocking);
        cudaEventCreateWithFlags(&ev1, cudaEventDisableTiming);
        cudaEventCreateWithFlags(&ev2, cudaEventDisableTiming);
        cudaFuncSetAttribute(k5_text, cudaFuncAttributeMaxDynamicSharedMemorySize, 110592);
        cudaFuncSetAttribute(k3a_s2d, cudaFuncAttributeMaxDynamicSharedMemorySize, 101376);
    }

    k1_f3p <<<192, 256>>>(f3, W3, b3);
    cudaEventRecord(ev1, 0);

    // text path (depends only on f3p)
    cudaStreamWaitEvent(s2, ev1, 0);
    k5_text<<<2048, 256, 110592, s2>>>(ftx);
    k6_comb<<<96,  256, 0, s2>>>();
    cudaEventRecord(ev2, s2);

    // 2D path
    k2_u   <<<288, 256>>>(W2);
    k_ured <<<24,  256>>>();
    k3a_s2d<<<256, 256, 101376>>>(f2);
    k3b_comb<<<32, 256>>>();
    k4_p2d <<<192, 256>>>(W2, b2);

    // join -> fused GEMM -> output
    cudaStreamWaitEvent(0, ev2, 0);
    k7_fused<<<576, 256>>>(Wf);
    k8a_red<<<96,  256>>>(bf);
    k8b_out<<<384, 256>>>(out);
}